// round 13
// baseline (speedup 1.0000x reference)
#include <cuda_runtime.h>
#include <cuda_fp16.h>
#include <cstdint>
#include <math.h>

#define TOKENS   2048
#define DMODEL   1024
#define HIDDEN   2048
#define NEXP     8
#define VOCABSZ  32000
#define LN_EPS   1e-5f

#define MT 128
#define NT 256
#define KCH 32
#define NSTG 4
// packed block sizes (bytes): A 128 rows x 80B, B 32 rows x 528B
#define ABLK_B   10240
#define BBLK_B   16896
#define ABLK_H   5120
#define BBLK_H   8448
#define STG2 (2 * (ABLK_B + BBLK_B))         // 54272 (two K-chunks per stage)
#define MBOFF (NSTG * STG2)                  // 217088
#define SMEM_SZ (MBOFF + 128)

#define NSLOTPAD 5120
#define SLOTTILES 40
#define NSM 152

// ---------------- scratch (device globals; no allocation allowed) ----------
__device__ float g_w  [TOKENS * 2];
__device__ int   g_eidx[TOKENS * 2];
__device__ int   g_slot[TOKENS * 2];
__device__ int   g_tokOfSlot[NSLOTPAD];
__device__ int   g_cnt[NEXP];
__device__ int   g_off[NEXP + 1];
__device__ float g_y  [NSLOTPAD * DMODEL];
// packed operands (SMEM-image blocks)
__device__ __align__(16) __half g_hpk [SLOTTILES * 32 * ABLK_H];  // FFN1 A
__device__ __align__(16) __half g_apk [SLOTTILES * 64 * ABLK_H];  // FFN2 A
__device__ __align__(16) __half g_xpk [16 * 32 * ABLK_H];         // head A
__device__ __align__(16) __half g_Whp [125 * 32 * BBLK_H];
__device__ __align__(16) __half g_W1p [NEXP * 8 * 32 * BBLK_H];
__device__ __align__(16) __half g_W2p [NEXP * 4 * 64 * BBLK_H];

// ---------------- helpers ----------------------------------------------------
__device__ __forceinline__ uint32_t h2u(__half2 h) {
    return *reinterpret_cast<uint32_t*>(&h);
}
__device__ __forceinline__ uint32_t smem_u32(const void* p) {
    uint32_t a;
    asm("{ .reg .u64 t; cvta.to.shared.u64 t, %1; cvt.u32.u64 %0, t; }"
        : "=r"(a) : "l"(p));
    return a;
}
__device__ __forceinline__ void mma_f16(float c[4], const uint32_t a[4],
                                        const uint32_t b[2]) {
    asm volatile(
        "mma.sync.aligned.m16n8k16.row.col.f32.f16.f16.f32 "
        "{%0,%1,%2,%3}, {%4,%5,%6,%7}, {%8,%9}, {%0,%1,%2,%3};"
        : "+f"(c[0]), "+f"(c[1]), "+f"(c[2]), "+f"(c[3])
        : "r"(a[0]), "r"(a[1]), "r"(a[2]), "r"(a[3]), "r"(b[0]), "r"(b[1]));
}
__device__ __forceinline__ void ldsm4(uint32_t r[4], uint32_t addr) {
    asm volatile("ldmatrix.sync.aligned.m8n8.x4.shared.b16 {%0,%1,%2,%3}, [%4];"
                 : "=r"(r[0]), "=r"(r[1]), "=r"(r[2]), "=r"(r[3]) : "r"(addr));
}
__device__ __forceinline__ void ldsm4t(uint32_t r[4], uint32_t addr) {
    asm volatile("ldmatrix.sync.aligned.m8n8.x4.trans.shared.b16 {%0,%1,%2,%3}, [%4];"
                 : "=r"(r[0]), "=r"(r[1]), "=r"(r[2]), "=r"(r[3]) : "r"(addr));
}
#define MBAR_INIT(a, n) \
    asm volatile("mbarrier.init.shared.b64 [%0], %1;" :: "r"((uint32_t)(a)), "r"((uint32_t)(n)) : "memory")
#define MBAR_EXPECT_TX(a, b) \
    asm volatile("mbarrier.arrive.expect_tx.shared.b64 _, [%0], %1;" :: "r"((uint32_t)(a)), "r"((uint32_t)(b)) : "memory")
#define MBAR_ARRIVE(a) \
    asm volatile("mbarrier.arrive.shared.b64 _, [%0];" :: "r"((uint32_t)(a)) : "memory")
#define MBAR_WAIT(a, par) do { \
    uint32_t _mb = (uint32_t)(a); uint32_t _pa = (uint32_t)(par); uint32_t _dn; \
    asm volatile("{\n\t.reg .pred p;\n\t" \
        "mbarrier.try_wait.parity.acquire.cta.shared::cta.b64 p, [%1], %2;\n\t" \
        "selp.b32 %0, 1, 0, p;\n\t}" : "=r"(_dn) : "r"(_mb), "r"(_pa) : "memory"); \
    if (!_dn) { \
        asm volatile("{\n\t.reg .pred P1;\n\t" \
            "WL_%=:\n\t" \
            "mbarrier.try_wait.parity.acquire.cta.shared::cta.b64 P1, [%0], %1, 0x989680;\n\t" \
            "@P1 bra.uni WD_%=;\n\t" \
            "bra.uni WL_%=;\n\t" \
            "WD_%=:\n\t}" :: "r"(_mb), "r"(_pa) : "memory"); \
    } } while (0)
__device__ __forceinline__ void bulk_ld(uint32_t dst, const void* src,
                                        uint32_t bytes, uint32_t mbar) {
    asm volatile(
        "cp.async.bulk.shared::cluster.global.mbarrier::complete_tx::bytes "
        "[%0], [%1], %2, [%3];"
        :: "r"(dst), "l"(src), "r"(bytes), "r"(mbar) : "memory");
}

// ---------------- fused: weight pack + gate ----------------------------------
#define WH_UNITS (125 * 32 * 32 * 32)
#define W1_UNITS (NEXP * 8 * 32 * 32 * 32)
#define W2_UNITS (NEXP * 4 * 64 * 32 * 32)
#define W_TOTAL  (WH_UNITS + W1_UNITS + W2_UNITS)
#define WBLOCKS  ((W_TOTAL + 255) / 256)

__global__ void prep_kernel(const int* __restrict__ x,
                            const float* __restrict__ embed,
                            const float* __restrict__ Wg,
                            const float* __restrict__ bg,
                            const float* __restrict__ Wh,
                            const float* __restrict__ W1,
                            const float* __restrict__ W2) {
    if (blockIdx.x < WBLOCKS) {
        int idx = blockIdx.x * blockDim.x + threadIdx.x;
        const float* src;
        __half* dst;
        if (idx < WH_UNITS) {
            int u = idx & 31, k = (idx >> 5) & 31, ch = (idx >> 10) & 31, st = idx >> 15;
            src = Wh + (size_t)(ch * 32 + k) * VOCABSZ + st * 256 + u * 8;
            dst = g_Whp + (size_t)(st * 32 + ch) * BBLK_H + k * 264 + u * 8;
        } else if (idx < WH_UNITS + W1_UNITS) {
            int i = idx - WH_UNITS;
            int u = i & 31, k = (i >> 5) & 31, ch = (i >> 10) & 31, st = (i >> 15) & 7, e = i >> 18;
            src = W1 + (size_t)e * DMODEL * HIDDEN + (size_t)(ch * 32 + k) * HIDDEN + st * 256 + u * 8;
            dst = g_W1p + (size_t)((e * 8 + st) * 32 + ch) * BBLK_H + k * 264 + u * 8;
        } else if (idx < W_TOTAL) {
            int i = idx - WH_UNITS - W1_UNITS;
            int u = i & 31, k = (i >> 5) & 31, ch = (i >> 10) & 63, st = (i >> 16) & 3, e = i >> 18;
            src = W2 + (size_t)e * HIDDEN * DMODEL + (size_t)(ch * 32 + k) * DMODEL + st * 256 + u * 8;
            dst = g_W2p + (size_t)((e * 4 + st) * 64 + ch) * BBLK_H + k * 264 + u * 8;
        } else return;
        float4 v0 = *(const float4*)src;
        float4 v1 = *(const float4*)(src + 4);
        uint4 o;
        o.x = h2u(__floats2half2_rn(v0.x, v0.y));
        o.y = h2u(__floats2half2_rn(v0.z, v0.w));
        o.z = h2u(__floats2half2_rn(v1.x, v1.y));
        o.w = h2u(__floats2half2_rn(v1.z, v1.w));
        *(uint4*)dst = o;
        return;
    }
    // ---- gate (one block per token) ----
    int t   = blockIdx.x - WBLOCKS;
    int tid = threadIdx.x;
    int row = x[t];
    float4 v = ((const float4*)(embed + (size_t)row * DMODEL))[tid];

    float p[NEXP];
#pragma unroll
    for (int e = 0; e < NEXP; e++) p[e] = 0.f;
    float hv[4] = {v.x, v.y, v.z, v.w};
    int d0 = tid * 4;
#pragma unroll
    for (int j = 0; j < 4; j++) {
        const float* wgr = Wg + (size_t)(d0 + j) * NEXP;
#pragma unroll
        for (int e = 0; e < NEXP; e++) p[e] += hv[j] * wgr[e];
    }
#pragma unroll
    for (int e = 0; e < NEXP; e++)
        for (int o = 16; o > 0; o >>= 1)
            p[e] += __shfl_xor_sync(0xffffffffu, p[e], o);

    __shared__ float red[8][NEXP];
    int warp = tid >> 5, lane = tid & 31;
    if (lane == 0)
#pragma unroll
        for (int e = 0; e < NEXP; e++) red[warp][e] = p[e];
    __syncthreads();

    if (tid == 0) {
        float g[NEXP];
#pragma unroll
        for (int e = 0; e < NEXP; e++) {
            g[e] = bg[e];
#pragma unroll
            for (int w = 0; w < 8; w++) g[e] += red[w][e];
        }
        float mx = g[0];
#pragma unroll
        for (int e = 1; e < NEXP; e++) mx = fmaxf(mx, g[e]);
        float s = 0.f, pr[NEXP];
#pragma unroll
        for (int e = 0; e < NEXP; e++) { pr[e] = expf(g[e] - mx); s += pr[e]; }
        float inv = 1.f / s;
#pragma unroll
        for (int e = 0; e < NEXP; e++) pr[e] *= inv;

        int i0 = 0;
#pragma unroll
        for (int e = 1; e < NEXP; e++) if (pr[e] > pr[i0]) i0 = e;
        int i1 = (i0 == 0) ? 1 : 0;
#pragma unroll
        for (int e = 0; e < NEXP; e++)
            if (e != i0 && pr[e] > pr[i1]) i1 = e;

        g_w[2 * t]     = pr[i0];  g_eidx[2 * t]     = i0;
        g_w[2 * t + 1] = pr[i1];  g_eidx[2 * t + 1] = i1;
    }
}

// ---------------- count + scan (128-aligned) + slot assignment ---------------
__global__ void scan_assign_kernel() {
    __shared__ int s_cnt[NEXP];
    __shared__ int s_off[NEXP + 1];
    __shared__ int s_cur[NEXP];
    int tid = threadIdx.x;
    for (int i = tid; i < NSLOTPAD; i += blockDim.x) g_tokOfSlot[i] = 0;
    if (tid < NEXP) { s_cnt[tid] = 0; s_cur[tid] = 0; }
    __syncthreads();
    for (int i = tid; i < TOKENS * 2; i += blockDim.x)
        atomicAdd(&s_cnt[g_eidx[i]], 1);
    __syncthreads();
    if (tid == 0) {
        s_off[0] = 0;
        for (int e = 0; e < NEXP; e++) {
            s_off[e + 1] = s_off[e] + ((s_cnt[e] + 127) & ~127);
            g_cnt[e] = s_cnt[e];
        }
        for (int e = 0; e <= NEXP; e++) g_off[e] = s_off[e];
    }
    __syncthreads();
    for (int t = tid; t < TOKENS; t += blockDim.x) {
#pragma unroll
        for (int k = 0; k < 2; k++) {
            int e = g_eidx[2 * t + k];
            int pos = atomicAdd(&s_cur[e], 1);
            int slot = s_off[e] + pos;
            g_slot[2 * t + k] = slot;
            g_tokOfSlot[slot] = t;
        }
    }
}

// ---------------- pack FFN1 A: embed rows (slot order) -> padded blocks -----
__global__ void pack_h_kernel(const int* __restrict__ x,
                              const float* __restrict__ embed) {
    int idx = blockIdx.x * blockDim.x + threadIdx.x;
    if (idx >= NSLOTPAD * 128) return;
    int slot = idx >> 7;
    int u = idx & 127;
    int ch = u >> 2, pos = u & 3;
    int tok = g_tokOfSlot[slot];
    int row = x[tok];
    const float* src = embed + (size_t)row * DMODEL + ch * 32 + pos * 8;
    float4 v0 = *(const float4*)src;
    float4 v1 = *(const float4*)(src + 4);
    uint4 o;
    o.x = h2u(__floats2half2_rn(v0.x, v0.y));
    o.y = h2u(__floats2half2_rn(v0.z, v0.w));
    o.z = h2u(__floats2half2_rn(v1.x, v1.y));
    o.w = h2u(__floats2half2_rn(v1.z, v1.w));
    __half* dst = g_hpk + (size_t)((slot >> 7) * 32 + ch) * ABLK_H + (slot & 127) * 40 + pos * 8;
    *(uint4*)dst = o;
}

// ---------------- combine + LN -> packed head A ------------------------------
__global__ void combine_ln_kernel(const float* __restrict__ gamma,
                                  const float* __restrict__ beta) {
    int t = blockIdx.x, tid = threadIdx.x;
    int s0 = g_slot[2 * t], s1 = g_slot[2 * t + 1];
    float w0 = g_w[2 * t], w1 = g_w[2 * t + 1];

    float4 a = ((const float4*)(g_y + (size_t)s0 * DMODEL))[tid];
    float4 b = ((const float4*)(g_y + (size_t)s1 * DMODEL))[tid];
    float4 c;
    c.x = w0 * a.x + w1 * b.x;  c.y = w0 * a.y + w1 * b.y;
    c.z = w0 * a.z + w1 * b.z;  c.w = w0 * a.w + w1 * b.w;

    float sum = c.x + c.y + c.z + c.w;
    float ssq = c.x*c.x + c.y*c.y + c.z*c.z + c.w*c.w;
    for (int o = 16; o > 0; o >>= 1) {
        sum += __shfl_xor_sync(0xffffffffu, sum, o);
        ssq += __shfl_xor_sync(0xffffffffu, ssq, o);
    }
    __shared__ float rs[8], rq[8];
    __shared__ float s_mu, s_rstd;
    int warp = tid >> 5, lane = tid & 31;
    if (lane == 0) { rs[warp] = sum; rq[warp] = ssq; }
    __syncthreads();
    if (tid == 0) {
        float S = 0.f, Q = 0.f;
#pragma unroll
        for (int w = 0; w < 8; w++) { S += rs[w]; Q += rq[w]; }
        float mu = S / (float)DMODEL;
        float var = Q / (float)DMODEL - mu * mu;
        s_mu = mu;
        s_rstd = rsqrtf(var + LN_EPS);
    }
    __syncthreads();
    float mu = s_mu, rstd = s_rstd;
    float4 g4 = ((const float4*)gamma)[tid];
    float4 b4 = ((const float4*)beta)[tid];
    uint2 o;
    o.x = h2u(__floats2half2_rn((c.x - mu) * rstd * g4.x + b4.x,
                                (c.y - mu) * rstd * g4.y + b4.y));
    o.y = h2u(__floats2half2_rn((c.z - mu) * rstd * g4.z + b4.z,
                                (c.w - mu) * rstd * g4.w + b4.w));
    int d0 = tid * 4;
    int ch = d0 >> 5, c2 = d0 & 31;
    __half* dst = g_xpk + (size_t)((t >> 7) * 32 + ch) * ABLK_H + (t & 127) * 40 + c2;
    *(uint2*)dst = o;
}

// ================== GEMM common fragment machinery ===========================
// layout: stage s = (ksAbs>>2)&3, sub = (ks>>1)&1, ksl = ks&1
#define LDSM_STEP(A, Bf, ksAbs)                                                \
    do {                                                                       \
        int _s = ((ksAbs) >> 2) & (NSTG - 1);                                  \
        int _sub = ((ksAbs) >> 1) & 1;                                         \
        int _ksl = (ksAbs) & 1;                                                \
        uint32_t _sb = smb + (uint32_t)_s * STG2;                              \
        uint32_t _ab = _sb + _sub * ABLK_B;                                    \
        uint32_t _bb = _sb + 2 * ABLK_B + _sub * BBLK_B;                       \
        _Pragma("unroll")                                                      \
        for (int _mb = 0; _mb < 4; _mb++)                                      \
            ldsm4(A[_mb], _ab + (uint32_t)((wmOff + _mb * 16 + aRow) * 5 +     \
                                           _ksl * 2 + aKu) * 16);             \
        _Pragma("unroll")                                                      \
        for (int _p = 0; _p < 2; _p++) {                                       \
            uint32_t _rr[4];                                                   \
            ldsm4t(_rr, _bb + (uint32_t)((_ksl * 16 + bK) * 33 + bNu +         \
                                         _p * 2) * 16);                       \
            Bf[2 * _p][0] = _rr[0]; Bf[2 * _p][1] = _rr[1];                    \
            Bf[2 * _p + 1][0] = _rr[2]; Bf[2 * _p + 1][1] = _rr[3];            \
        }                                                                      \
    } while (0)

#define MMA_STEP(A, Bf)                                                        \
    do {                                                                       \
        _Pragma("unroll")                                                      \
        for (int _mb = 0; _mb < 4; _mb++)                                      \
            _Pragma("unroll")                                                  \
            for (int _nb = 0; _nb < 4; _nb++)                                  \
                mma_f16(acc[_mb][_nb], A[_mb], Bf[_nb]);                       \
    } while (0)

// pipeline step: prefetch frags for (ksAbs+1), then MMA ksAbs.
// Every stage's release fires exactly once on the (_ksn&3)==3 path
// (totKs is a multiple of 4, so _ksn=totKs-1 covers the last stage).
#define PIPE_STEP(curA, curB, nxtA, nxtB, ksAbs, totKs, gTotal)                \
    do {                                                                       \
        int _ksn = (ksAbs) + 1;                                                \
        if (_ksn < (totKs)) {                                                  \
            if ((_ksn & 3) == 0) {                                             \
                int _g = _ksn >> 2;                                            \
                MBAR_WAIT(mbF + (_g & 3) * 8, (_g >> 2) & 1);                  \
            }                                                                  \
            LDSM_STEP(nxtA, nxtB, _ksn);                                       \
            if ((_ksn & 3) == 3) {                                             \
                int _g = _ksn >> 2;                                            \
                __syncwarp();                                                  \
                if (lane == 0) MBAR_ARRIVE(mbE + (_g & 3) * 8);                \
                if (tid == 0 && _g + NSTG < (gTotal)) {                        \
                    MBAR_WAIT(mbE + (_g & 3) * 8, (_g >> 2) & 1);              \
                    issue(_g + NSTG);                                          \
                }                                                              \
            }                                                                  \
        }                                                                      \
        MMA_STEP(curA, curB);                                                  \
    } while (0)

// ---------------- grouped fp16 GEMM (FFN1/FFN2), ks-pipelined ----------------
template <int K, int N, bool RELU, int OUT>
__global__ void __launch_bounds__(512, 1)
bgemm(const __half* __restrict__ Apk, const __half* __restrict__ Bpk,
      const float* __restrict__ biasAll, void* __restrict__ Cout) {
    extern __shared__ __align__(128) char smc[];
    const int NCH = K / KCH;
    const int NC2 = K / (2 * KCH);
    const int TOTKS = K / 16;
    const int NSTRIPE = N / NT;

    int e = blockIdx.z;
    int rowOff = g_off[e];
    int cnt = g_cnt[e];
    int mTile = blockIdx.y;
    int nTile = blockIdx.x;
    int rowBlock = mTile * MT;
    if (rowBlock >= cnt) return;
    int colBlock = nTile * NT;
    int gmTile = (rowOff >> 7) + mTile;

    const __half* Ablk = Apk + (size_t)gmTile * NCH * ABLK_H;
    const __half* Bblk = Bpk + (size_t)(e * NSTRIPE + nTile) * NCH * BBLK_H;
    const float* bias = biasAll + (size_t)e * N;

    int tid = threadIdx.x;
    int wid = tid >> 5, lane = tid & 31;
    int wm = wid >> 3, wn = wid & 7;
    int wmOff = wm * 64, wnOff = wn * 32;
    int g = lane >> 2, tg = lane & 3;
    int b3 = lane >> 3, r8 = lane & 7;
    int aRow = (b3 & 1) * 8 + r8;
    int aKu  = b3 >> 1;
    int bK   = (b3 & 1) * 8 + r8;
    int bNu  = (b3 >> 1) + (wnOff >> 3);

    uint32_t smb = smem_u32(smc);
    uint32_t mbF = smb + MBOFF;
    uint32_t mbE = smb + MBOFF + 64;

    if (tid == 0) {
#pragma unroll
        for (int s = 0; s < NSTG; s++) {
            MBAR_INIT(mbF + s * 8, 1);
            MBAR_INIT(mbE + s * 8, 16);
        }
    }
    __syncthreads();

    auto issue = [&](int c2) {
        int s = c2 & (NSTG - 1);
        uint32_t stg = smb + (uint32_t)s * STG2;
        uint32_t mb = mbF + s * 8;
        MBAR_EXPECT_TX(mb, STG2);
        bulk_ld(stg, Ablk + (size_t)(2 * c2) * ABLK_H, 2 * ABLK_B, mb);
        bulk_ld(stg + 2 * ABLK_B, Bblk + (size_t)(2 * c2) * BBLK_H, 2 * BBLK_B, mb);
    };

    if (tid == 0) {
#pragma unroll
        for (int c0 = 0; c0 < NSTG; c0++) issue(c0);
    }

    float acc[4][4][4];
#pragma unroll
    for (int i = 0; i < 4; i++)
#pragma unroll
        for (int j = 0; j < 4; j++)
#pragma unroll
            for (int q = 0; q < 4; q++) acc[i][j][q] = 0.f;

    uint32_t A0[4][4], A1[4][4];
    uint32_t B0[4][2], B1[4][2];

    // prologue: wait stage 0, load ks0
    MBAR_WAIT(mbF + 0, 0);
    LDSM_STEP(A0, B0, 0);

    for (int ks = 0; ks < TOTKS; ks += 2) {
        PIPE_STEP(A0, B0, A1, B1, ks,     TOTKS, NC2);
        PIPE_STEP(A1, B1, A0, B0, ks + 1, TOTKS, NC2);
    }

    // epilogue
#pragma unroll
    for (int nb = 0; nb < 4; nb++) {
        int col = colBlock + wnOff + nb * 8 + tg * 2;
        float2 bv = *(const float2*)(bias + col);
#pragma unroll
        for (int mb = 0; mb < 4; mb++) {
            int mr = wmOff + mb * 16 + g;
#pragma unroll
            for (int h = 0; h < 2; h++) {
                int rr2 = mr + h * 8;
                if (rowBlock + rr2 < cnt) {
                    float ox = acc[mb][nb][2 * h]     + bv.x;
                    float oy = acc[mb][nb][2 * h + 1] + bv.y;
                    if (RELU) { ox = fmaxf(ox, 0.f); oy = fmaxf(oy, 0.f); }
                    if (OUT == 1) {
                        int R = rowOff + rowBlock + rr2;
                        __half* dst = (__half*)Cout +
                            (size_t)((R >> 7) * (N / 32) + (col >> 5)) * ABLK_H +
                            (R & 127) * 40 + (col & 31);
                        *(__half2*)dst = __floats2half2_rn(ox, oy);
                    } else {
                        size_t ro = (size_t)(rowOff + rowBlock + rr2) * N + col;
                        *(float2*)((float*)Cout + ro) = make_float2(ox, oy);
                    }
                }
            }
        }
    }
}

// ---------------- persistent head GEMM, ks-pipelined --------------------------
#define H_NCH   (DMODEL / KCH)        // 32
#define H_NC2   (DMODEL / (2 * KCH))  // 16
#define H_TOTKS (DMODEL / 16)         // 64
#define H_TM    16
#define H_TN    125
#define H_NTILES (H_TM * H_TN)

__global__ void __launch_bounds__(512, 1)
hgemm_persist(const __half* __restrict__ Apk, const __half* __restrict__ Bpk,
              const float* __restrict__ bias, float* __restrict__ out) {
    extern __shared__ __align__(128) char smc[];
    int bid = blockIdx.x;
    int nCTA = gridDim.x;

    int nMy = (bid < H_NTILES) ? ((H_NTILES - 1 - bid) / nCTA + 1) : 0;
    if (nMy == 0) return;
    int totalStages = nMy * H_NC2;

    int tid = threadIdx.x;
    int wid = tid >> 5, lane = tid & 31;
    int wm = wid >> 3, wn = wid & 7;
    int wmOff = wm * 64, wnOff = wn * 32;
    int g = lane >> 2, tg = lane & 3;
    int b3 = lane >> 3, r8 = lane & 7;
    int aRow = (b3 & 1) * 8 + r8;
    int aKu  = b3 >> 1;
    int bK   = (b3 & 1) * 8 + r8;
    int bNu  = (b3 >> 1) + (wnOff >> 3);

    uint32_t smb = smem_u32(smc);
    uint32_t mbF = smb + MBOFF;
    uint32_t mbE = smb + MBOFF + 64;

    if (tid == 0) {
#pragma unroll
        for (int s = 0; s < NSTG; s++) {
            MBAR_INIT(mbF + s * 8, 1);
            MBAR_INIT(mbE + s * 8, 16);
        }
    }
    __syncthreads();

    auto issue = [&](int gc) {
        int s = gc & (NSTG - 1);
        int tileSeq = gc / H_NC2;
        int c2 = gc - tileSeq * H_NC2;
        int tile = bid + tileSeq * nCTA;
        int m = tile & (H_TM - 1);
        int n = tile >> 4;
        const __half* Ab = Apk + ((size_t)m * H_NCH + 2 * c2) * ABLK_H;
        const __half* Bb = Bpk + ((size_t)n * H_NCH + 2 * c2) * BBLK_H;
        uint32_t stg = smb + (uint32_t)s * STG2;
        uint32_t mb = mbF + s * 8;
        MBAR_EXPECT_TX(mb, STG2);
        bulk_ld(stg, Ab, 2 * ABLK_B, mb);
        bulk_ld(stg + 2 * ABLK_B, Bb, 2 * BBLK_B, mb);
    };

    if (tid == 0) {
        int pre = totalStages < NSTG ? totalStages : NSTG;
        for (int c0 = 0; c0 < pre; c0++) issue(c0);
    }

    uint32_t A0[4][4], A1[4][4];
    uint32_t B0[4][2], B1[4][2];
    int gBase = 0;

    for (int tile = bid; tile < H_NTILES; tile += nCTA) {
        int m = tile & (H_TM - 1);
        int n = tile >> 4;

        float acc[4][4][4];
#pragma unroll
        for (int i = 0; i < 4; i++)
#pragma unroll
            for (int j = 0; j < 4; j++)
#pragma unroll
                for (int q = 0; q < 4; q++) acc[i][j][q] = 0.f;

        // per-tile prologue: wait this tile's first stage, load its ks0
        MBAR_WAIT(mbF + (gBase & 3) * 8, (gBase >> 2) & 1);
        LDSM_STEP(A0, B0, gBase * 4);

        for (int ks = 0; ks < H_TOTKS; ks += 2) {
            PIPE_STEP(A0, B0, A1, B1, gBase * 4 + ks,
                      gBase * 4 + H_TOTKS, totalStages);
            PIPE_STEP(A1, B1, A0, B0, gBase * 4 + ks + 1,
                      gBase * 4 + H_TOTKS, totalStages);
        }
        gBase += H_NC2;

        // epilogue
        int rowBase = m * MT;
        int colBase = n * NT;
#pragma unroll
        for (int nb = 0; nb < 4; nb++) {
            int col = colBase + wnOff + nb * 8 + tg * 2;
            float2 bv = *(const float2*)(bias + col);
#pragma unroll
            for (int mb = 0; mb < 4; mb++) {
                int mr = rowBase + wmOff + mb * 16 + g;
#pragma unroll
                for (int h = 0; h < 2; h++) {
                    float ox = acc[mb][nb][2 * h]     + bv.x;
                    float oy = acc[mb][nb][2 * h + 1] + bv.y;
                    *(float2*)(out + (size_t)(mr + h * 8) * VOCABSZ + col) =
                        make_float2(ox, oy);
                }
            }
        }
    }
}

// ---------------- launch ----------------------------------------------------
extern "C" void kernel_launch(void* const* d_in, const int* in_sizes, int n_in,
                              void* d_out, int out_size) {
    const int*   x     = (const int*)  d_in[0];
    const float* embed = (const float*)d_in[1];
    const float* Wg    = (const float*)d_in[2];
    const float* bg    = (const float*)d_in[3];
    const float* W1    = (const float*)d_in[4];
    const float* b1    = (const float*)d_in[5];
    const float* W2    = (const float*)d_in[6];
    const float* b2    = (const float*)d_in[7];
    const float* gamma = (const float*)d_in[8];
    const float* beta  = (const float*)d_in[9];
    const float* Wh    = (const float*)d_in[10];
    const float* bh    = (const float*)d_in[11];
    float* out = (float*)d_out;

    __half *p_hpk, *p_apk, *p_xpk, *p_Whp, *p_W1p, *p_W2p;
    float *p_y;
    cudaGetSymbolAddress((void**)&p_hpk, g_hpk);
    cudaGetSymbolAddress((void**)&p_apk, g_apk);
    cudaGetSymbolAddress((void**)&p_xpk, g_xpk);
    cudaGetSymbolAddress((void**)&p_Whp, g_Whp);
    cudaGetSymbolAddress((void**)&p_W1p, g_W1p);
    cudaGetSymbolAddress((void**)&p_W2p, g_W2p);
    cudaGetSymbolAddress((void**)&p_y,   g_y);

    cudaFuncSetAttribute((const void*)bgemm<DMODEL, HIDDEN, true, 1>,
                         cudaFuncAttributeMaxDynamicSharedMemorySize, SMEM_SZ);
    cudaFuncSetAttribute((const void*)bgemm<HIDDEN, DMODEL, false, 0>,
                         cudaFuncAttributeMaxDynamicSharedMemorySize, SMEM_SZ);
    cudaFuncSetAttribute((const void*)hgemm_persist,
                         cudaFuncAttributeMaxDynamicSharedMemorySize, SMEM_SZ);

    prep_kernel<<<WBLOCKS + TOKENS, 256>>>(x, embed, Wg, bg, Wh, W1, W2);
    scan_assign_kernel<<<1, 1024>>>();
    pack_h_kernel<<<(NSLOTPAD * 128 + 255) / 256, 256>>>(x, embed);

    bgemm<DMODEL, HIDDEN, true, 1>
        <<<dim3(HIDDEN / NT, 16, NEXP), 512, SMEM_SZ>>>(p_hpk, p_W1p, b1, p_apk);
    bgemm<HIDDEN, DMODEL, false, 0>
        <<<dim3(DMODEL / NT, 16, NEXP), 512, SMEM_SZ>>>(p_apk, p_W2p, b2, p_y);

    combine_ln_kernel<<<TOKENS, 256>>>(gamma, beta);

    hgemm_persist<<<NSM, 512, SMEM_SZ>>>(p_xpk, p_Whp, bh, out);
}

// round 14
// speedup vs baseline: 1.0466x; 1.0466x over previous
#include <cuda_runtime.h>
#include <cuda_fp16.h>
#include <cstdint>
#include <math.h>

#define TOKENS   2048
#define DMODEL   1024
#define HIDDEN   2048
#define NEXP     8
#define VOCABSZ  32000
#define LN_EPS   1e-5f

#define MT 128
#define NT 256
#define KCH 32
#define NSTG 4
// packed block sizes (bytes): A 128 rows x 80B, B 32 rows x 528B
#define ABLK_B   10240
#define BBLK_B   16896
#define ABLK_H   5120
#define BBLK_H   8448
#define STG2 (2 * (ABLK_B + BBLK_B))         // 54272 (two K-chunks per stage)
#define MBOFF (NSTG * STG2)                  // 217088
#define SMEM_SZ (MBOFF + 128)

#define NSLOTPAD 5120
#define SLOTTILES 40
#define NSM 152

// ---------------- scratch (device globals; no allocation allowed) ----------
__device__ float g_w  [TOKENS * 2];
__device__ int   g_eidx[TOKENS * 2];
__device__ int   g_slot[TOKENS * 2];
__device__ int   g_tokOfSlot[NSLOTPAD];
__device__ int   g_cnt[NEXP];
__device__ int   g_off[NEXP + 1];
__device__ int   g_mOff[NEXP];    // m-tile prefix offsets
__device__ int   g_mtot;          // total m-tiles
__device__ float g_y  [NSLOTPAD * DMODEL];
// packed operands (SMEM-image blocks)
__device__ __align__(16) __half g_hpk [SLOTTILES * 32 * ABLK_H];  // FFN1 A
__device__ __align__(16) __half g_apk [SLOTTILES * 64 * ABLK_H];  // FFN2 A
__device__ __align__(16) __half g_xpk [16 * 32 * ABLK_H];         // head A
__device__ __align__(16) __half g_Whp [125 * 32 * BBLK_H];
__device__ __align__(16) __half g_W1p [NEXP * 8 * 32 * BBLK_H];
__device__ __align__(16) __half g_W2p [NEXP * 4 * 64 * BBLK_H];

// ---------------- helpers ----------------------------------------------------
__device__ __forceinline__ uint32_t h2u(__half2 h) {
    return *reinterpret_cast<uint32_t*>(&h);
}
__device__ __forceinline__ uint32_t smem_u32(const void* p) {
    uint32_t a;
    asm("{ .reg .u64 t; cvta.to.shared.u64 t, %1; cvt.u32.u64 %0, t; }"
        : "=r"(a) : "l"(p));
    return a;
}
__device__ __forceinline__ void mma_f16(float c[4], const uint32_t a[4],
                                        const uint32_t b[2]) {
    asm volatile(
        "mma.sync.aligned.m16n8k16.row.col.f32.f16.f16.f32 "
        "{%0,%1,%2,%3}, {%4,%5,%6,%7}, {%8,%9}, {%0,%1,%2,%3};"
        : "+f"(c[0]), "+f"(c[1]), "+f"(c[2]), "+f"(c[3])
        : "r"(a[0]), "r"(a[1]), "r"(a[2]), "r"(a[3]), "r"(b[0]), "r"(b[1]));
}
__device__ __forceinline__ void ldsm4(uint32_t r[4], uint32_t addr) {
    asm volatile("ldmatrix.sync.aligned.m8n8.x4.shared.b16 {%0,%1,%2,%3}, [%4];"
                 : "=r"(r[0]), "=r"(r[1]), "=r"(r[2]), "=r"(r[3]) : "r"(addr));
}
__device__ __forceinline__ void ldsm4t(uint32_t r[4], uint32_t addr) {
    asm volatile("ldmatrix.sync.aligned.m8n8.x4.trans.shared.b16 {%0,%1,%2,%3}, [%4];"
                 : "=r"(r[0]), "=r"(r[1]), "=r"(r[2]), "=r"(r[3]) : "r"(addr));
}
#define MBAR_INIT(a, n) \
    asm volatile("mbarrier.init.shared.b64 [%0], %1;" :: "r"((uint32_t)(a)), "r"((uint32_t)(n)) : "memory")
#define MBAR_EXPECT_TX(a, b) \
    asm volatile("mbarrier.arrive.expect_tx.shared.b64 _, [%0], %1;" :: "r"((uint32_t)(a)), "r"((uint32_t)(b)) : "memory")
#define MBAR_ARRIVE(a) \
    asm volatile("mbarrier.arrive.shared.b64 _, [%0];" :: "r"((uint32_t)(a)) : "memory")
#define MBAR_WAIT(a, par) do { \
    uint32_t _mb = (uint32_t)(a); uint32_t _pa = (uint32_t)(par); uint32_t _dn; \
    asm volatile("{\n\t.reg .pred p;\n\t" \
        "mbarrier.try_wait.parity.acquire.cta.shared::cta.b64 p, [%1], %2;\n\t" \
        "selp.b32 %0, 1, 0, p;\n\t}" : "=r"(_dn) : "r"(_mb), "r"(_pa) : "memory"); \
    if (!_dn) { \
        asm volatile("{\n\t.reg .pred P1;\n\t" \
            "WL_%=:\n\t" \
            "mbarrier.try_wait.parity.acquire.cta.shared::cta.b64 P1, [%0], %1, 0x989680;\n\t" \
            "@P1 bra.uni WD_%=;\n\t" \
            "bra.uni WL_%=;\n\t" \
            "WD_%=:\n\t}" :: "r"(_mb), "r"(_pa) : "memory"); \
    } } while (0)
__device__ __forceinline__ void bulk_ld(uint32_t dst, const void* src,
                                        uint32_t bytes, uint32_t mbar) {
    asm volatile(
        "cp.async.bulk.shared::cluster.global.mbarrier::complete_tx::bytes "
        "[%0], [%1], %2, [%3];"
        :: "r"(dst), "l"(src), "r"(bytes), "r"(mbar) : "memory");
}

// ---------------- fused: weight pack + gate ----------------------------------
#define WH_UNITS (125 * 32 * 32 * 32)
#define W1_UNITS (NEXP * 8 * 32 * 32 * 32)
#define W2_UNITS (NEXP * 4 * 64 * 32 * 32)
#define W_TOTAL  (WH_UNITS + W1_UNITS + W2_UNITS)
#define WBLOCKS  ((W_TOTAL + 255) / 256)

__global__ void prep_kernel(const int* __restrict__ x,
                            const float* __restrict__ embed,
                            const float* __restrict__ Wg,
                            const float* __restrict__ bg,
                            const float* __restrict__ Wh,
                            const float* __restrict__ W1,
                            const float* __restrict__ W2) {
    if (blockIdx.x < WBLOCKS) {
        int idx = blockIdx.x * blockDim.x + threadIdx.x;
        const float* src;
        __half* dst;
        if (idx < WH_UNITS) {
            int u = idx & 31, k = (idx >> 5) & 31, ch = (idx >> 10) & 31, st = idx >> 15;
            src = Wh + (size_t)(ch * 32 + k) * VOCABSZ + st * 256 + u * 8;
            dst = g_Whp + (size_t)(st * 32 + ch) * BBLK_H + k * 264 + u * 8;
        } else if (idx < WH_UNITS + W1_UNITS) {
            int i = idx - WH_UNITS;
            int u = i & 31, k = (i >> 5) & 31, ch = (i >> 10) & 31, st = (i >> 15) & 7, e = i >> 18;
            src = W1 + (size_t)e * DMODEL * HIDDEN + (size_t)(ch * 32 + k) * HIDDEN + st * 256 + u * 8;
            dst = g_W1p + (size_t)((e * 8 + st) * 32 + ch) * BBLK_H + k * 264 + u * 8;
        } else if (idx < W_TOTAL) {
            int i = idx - WH_UNITS - W1_UNITS;
            int u = i & 31, k = (i >> 5) & 31, ch = (i >> 10) & 63, st = (i >> 16) & 3, e = i >> 18;
            src = W2 + (size_t)e * HIDDEN * DMODEL + (size_t)(ch * 32 + k) * DMODEL + st * 256 + u * 8;
            dst = g_W2p + (size_t)((e * 4 + st) * 64 + ch) * BBLK_H + k * 264 + u * 8;
        } else return;
        float4 v0 = *(const float4*)src;
        float4 v1 = *(const float4*)(src + 4);
        uint4 o;
        o.x = h2u(__floats2half2_rn(v0.x, v0.y));
        o.y = h2u(__floats2half2_rn(v0.z, v0.w));
        o.z = h2u(__floats2half2_rn(v1.x, v1.y));
        o.w = h2u(__floats2half2_rn(v1.z, v1.w));
        *(uint4*)dst = o;
        return;
    }
    // ---- gate (one block per token) ----
    int t   = blockIdx.x - WBLOCKS;
    int tid = threadIdx.x;
    int row = x[t];
    float4 v = ((const float4*)(embed + (size_t)row * DMODEL))[tid];

    float p[NEXP];
#pragma unroll
    for (int e = 0; e < NEXP; e++) p[e] = 0.f;
    float hv[4] = {v.x, v.y, v.z, v.w};
    int d0 = tid * 4;
#pragma unroll
    for (int j = 0; j < 4; j++) {
        const float* wgr = Wg + (size_t)(d0 + j) * NEXP;
#pragma unroll
        for (int e = 0; e < NEXP; e++) p[e] += hv[j] * wgr[e];
    }
#pragma unroll
    for (int e = 0; e < NEXP; e++)
        for (int o = 16; o > 0; o >>= 1)
            p[e] += __shfl_xor_sync(0xffffffffu, p[e], o);

    __shared__ float red[8][NEXP];
    int warp = tid >> 5, lane = tid & 31;
    if (lane == 0)
#pragma unroll
        for (int e = 0; e < NEXP; e++) red[warp][e] = p[e];
    __syncthreads();

    if (tid == 0) {
        float g[NEXP];
#pragma unroll
        for (int e = 0; e < NEXP; e++) {
            g[e] = bg[e];
#pragma unroll
            for (int w = 0; w < 8; w++) g[e] += red[w][e];
        }
        float mx = g[0];
#pragma unroll
        for (int e = 1; e < NEXP; e++) mx = fmaxf(mx, g[e]);
        float s = 0.f, pr[NEXP];
#pragma unroll
        for (int e = 0; e < NEXP; e++) { pr[e] = expf(g[e] - mx); s += pr[e]; }
        float inv = 1.f / s;
#pragma unroll
        for (int e = 0; e < NEXP; e++) pr[e] *= inv;

        int i0 = 0;
#pragma unroll
        for (int e = 1; e < NEXP; e++) if (pr[e] > pr[i0]) i0 = e;
        int i1 = (i0 == 0) ? 1 : 0;
#pragma unroll
        for (int e = 0; e < NEXP; e++)
            if (e != i0 && pr[e] > pr[i1]) i1 = e;

        g_w[2 * t]     = pr[i0];  g_eidx[2 * t]     = i0;
        g_w[2 * t + 1] = pr[i1];  g_eidx[2 * t + 1] = i1;
    }
}

// ---------------- count + scan (128-aligned) + slot assignment ---------------
__global__ void scan_assign_kernel() {
    __shared__ int s_cnt[NEXP];
    __shared__ int s_off[NEXP + 1];
    __shared__ int s_cur[NEXP];
    int tid = threadIdx.x;
    for (int i = tid; i < NSLOTPAD; i += blockDim.x) g_tokOfSlot[i] = 0;
    if (tid < NEXP) { s_cnt[tid] = 0; s_cur[tid] = 0; }
    __syncthreads();
    for (int i = tid; i < TOKENS * 2; i += blockDim.x)
        atomicAdd(&s_cnt[g_eidx[i]], 1);
    __syncthreads();
    if (tid == 0) {
        s_off[0] = 0;
        for (int e = 0; e < NEXP; e++) {
            s_off[e + 1] = s_off[e] + ((s_cnt[e] + 127) & ~127);
            g_cnt[e] = s_cnt[e];
        }
        for (int e = 0; e <= NEXP; e++) g_off[e] = s_off[e];
        for (int e = 0; e < NEXP; e++) g_mOff[e] = s_off[e] >> 7;
        g_mtot = s_off[NEXP] >> 7;
    }
    __syncthreads();
    for (int t = tid; t < TOKENS; t += blockDim.x) {
#pragma unroll
        for (int k = 0; k < 2; k++) {
            int e = g_eidx[2 * t + k];
            int pos = atomicAdd(&s_cur[e], 1);
            int slot = s_off[e] + pos;
            g_slot[2 * t + k] = slot;
            g_tokOfSlot[slot] = t;
        }
    }
}

// ---------------- pack FFN1 A: embed rows (slot order) -> padded blocks -----
__global__ void pack_h_kernel(const int* __restrict__ x,
                              const float* __restrict__ embed) {
    int idx = blockIdx.x * blockDim.x + threadIdx.x;
    if (idx >= NSLOTPAD * 128) return;
    int slot = idx >> 7;
    int u = idx & 127;
    int ch = u >> 2, pos = u & 3;
    int tok = g_tokOfSlot[slot];
    int row = x[tok];
    const float* src = embed + (size_t)row * DMODEL + ch * 32 + pos * 8;
    float4 v0 = *(const float4*)src;
    float4 v1 = *(const float4*)(src + 4);
    uint4 o;
    o.x = h2u(__floats2half2_rn(v0.x, v0.y));
    o.y = h2u(__floats2half2_rn(v0.z, v0.w));
    o.z = h2u(__floats2half2_rn(v1.x, v1.y));
    o.w = h2u(__floats2half2_rn(v1.z, v1.w));
    __half* dst = g_hpk + (size_t)((slot >> 7) * 32 + ch) * ABLK_H + (slot & 127) * 40 + pos * 8;
    *(uint4*)dst = o;
}

// ---------------- combine + LN -> packed head A ------------------------------
__global__ void combine_ln_kernel(const float* __restrict__ gamma,
                                  const float* __restrict__ beta) {
    int t = blockIdx.x, tid = threadIdx.x;
    int s0 = g_slot[2 * t], s1 = g_slot[2 * t + 1];
    float w0 = g_w[2 * t], w1 = g_w[2 * t + 1];

    float4 a = ((const float4*)(g_y + (size_t)s0 * DMODEL))[tid];
    float4 b = ((const float4*)(g_y + (size_t)s1 * DMODEL))[tid];
    float4 c;
    c.x = w0 * a.x + w1 * b.x;  c.y = w0 * a.y + w1 * b.y;
    c.z = w0 * a.z + w1 * b.z;  c.w = w0 * a.w + w1 * b.w;

    float sum = c.x + c.y + c.z + c.w;
    float ssq = c.x*c.x + c.y*c.y + c.z*c.z + c.w*c.w;
    for (int o = 16; o > 0; o >>= 1) {
        sum += __shfl_xor_sync(0xffffffffu, sum, o);
        ssq += __shfl_xor_sync(0xffffffffu, ssq, o);
    }
    __shared__ float rs[8], rq[8];
    __shared__ float s_mu, s_rstd;
    int warp = tid >> 5, lane = tid & 31;
    if (lane == 0) { rs[warp] = sum; rq[warp] = ssq; }
    __syncthreads();
    if (tid == 0) {
        float S = 0.f, Q = 0.f;
#pragma unroll
        for (int w = 0; w < 8; w++) { S += rs[w]; Q += rq[w]; }
        float mu = S / (float)DMODEL;
        float var = Q / (float)DMODEL - mu * mu;
        s_mu = mu;
        s_rstd = rsqrtf(var + LN_EPS);
    }
    __syncthreads();
    float mu = s_mu, rstd = s_rstd;
    float4 g4 = ((const float4*)gamma)[tid];
    float4 b4 = ((const float4*)beta)[tid];
    uint2 o;
    o.x = h2u(__floats2half2_rn((c.x - mu) * rstd * g4.x + b4.x,
                                (c.y - mu) * rstd * g4.y + b4.y));
    o.y = h2u(__floats2half2_rn((c.z - mu) * rstd * g4.z + b4.z,
                                (c.w - mu) * rstd * g4.w + b4.w));
    int d0 = tid * 4;
    int ch = d0 >> 5, c2 = d0 & 31;
    __half* dst = g_xpk + (size_t)((t >> 7) * 32 + ch) * ABLK_H + (t & 127) * 40 + c2;
    *(uint2*)dst = o;
}

// ============ shared per-stage mainloop body (Round-11 proven form) =========
// consumes stage sIdx: sub0 (ks0,ks1) then sub1 (ks0,ks1); releases empty[sIdx]
// after the last ldsm of sub1.
#define DO_STAGE(sIdx)                                                         \
    do {                                                                       \
        uint32_t sbase = smb + (uint32_t)(sIdx) * STG2;                        \
        {                                                                      \
            uint32_t ab = sbase;                                               \
            uint32_t bb = sbase + 2 * ABLK_B;                                  \
            _Pragma("unroll")                                                  \
            for (int ks = 0; ks < 2; ks++) {                                   \
                _Pragma("unroll")                                              \
                for (int mb = 0; mb < 4; mb++)                                 \
                    ldsm4(af[0][mb], ab + (uint32_t)((wmOff + mb * 16 + aRow) * 5 + ks * 2 + aKu) * 16); \
                _Pragma("unroll")                                              \
                for (int p = 0; p < 2; p++) {                                  \
                    uint32_t rr[4];                                            \
                    ldsm4t(rr, bb + (uint32_t)((ks * 16 + bK) * 33 + bNu + p * 2) * 16); \
                    bf[0][2 * p][0] = rr[0]; bf[0][2 * p][1] = rr[1];          \
                    bf[0][2 * p + 1][0] = rr[2]; bf[0][2 * p + 1][1] = rr[3];  \
                }                                                              \
                _Pragma("unroll")                                              \
                for (int mb = 0; mb < 4; mb++)                                 \
                    _Pragma("unroll")                                          \
                    for (int nb = 0; nb < 4; nb++)                             \
                        mma_f16(acc[mb][nb], af[0][mb], bf[0][nb]);            \
            }                                                                  \
        }                                                                      \
        {                                                                      \
            uint32_t ab = sbase + ABLK_B;                                      \
            uint32_t bb = sbase + 2 * ABLK_B + BBLK_B;                         \
            _Pragma("unroll")                                                  \
            for (int ks = 0; ks < 2; ks++) {                                   \
                _Pragma("unroll")                                              \
                for (int mb = 0; mb < 4; mb++)                                 \
                    ldsm4(af[1][mb], ab + (uint32_t)((wmOff + mb * 16 + aRow) * 5 + ks * 2 + aKu) * 16); \
                _Pragma("unroll")                                              \
                for (int p = 0; p < 2; p++) {                                  \
                    uint32_t rr[4];                                            \
                    ldsm4t(rr, bb + (uint32_t)((ks * 16 + bK) * 33 + bNu + p * 2) * 16); \
                    bf[1][2 * p][0] = rr[0]; bf[1][2 * p][1] = rr[1];          \
                    bf[1][2 * p + 1][0] = rr[2]; bf[1][2 * p + 1][1] = rr[3];  \
                }                                                              \
                if (ks == 1) {                                                 \
                    __syncwarp();                                              \
                    if (lane == 0) MBAR_ARRIVE(mbE + (sIdx) * 8);              \
                }                                                              \
                _Pragma("unroll")                                              \
                for (int mb = 0; mb < 4; mb++)                                 \
                    _Pragma("unroll")                                          \
                    for (int nb = 0; nb < 4; nb++)                             \
                        mma_f16(acc[mb][nb], af[1][mb], bf[1][nb]);            \
            }                                                                  \
        }                                                                      \
    } while (0)

// ---------------- persistent grouped fp16 GEMM (FFN1/FFN2) -------------------
// OUT: 0 = fp32 plain rows (g_y), 1 = half packed blocks (next GEMM's A)
template <int K, int N, bool RELU, int OUT>
__global__ void __launch_bounds__(512, 1)
fgemm_persist(const __half* __restrict__ Apk, const __half* __restrict__ Bpk,
              const float* __restrict__ biasAll, void* __restrict__ Cout) {
    extern __shared__ __align__(128) char smc[];
    const int NCH = K / KCH;
    const int NC2 = K / (2 * KCH);
    const int NSTRIPE = N / NT;

    int bid = blockIdx.x;
    int nCTA = gridDim.x;
    int mtot = g_mtot;
    int ntiles = mtot * NSTRIPE;
    int nMy = (bid < ntiles) ? ((ntiles - 1 - bid) / nCTA + 1) : 0;
    if (nMy == 0) return;
    int totalStages = nMy * NC2;

    int tid = threadIdx.x;
    int wid = tid >> 5, lane = tid & 31;
    int wm = wid >> 3, wn = wid & 7;
    int wmOff = wm * 64, wnOff = wn * 32;
    int g = lane >> 2, tg = lane & 3;
    int b3 = lane >> 3, r8 = lane & 7;
    int aRow = (b3 & 1) * 8 + r8;
    int aKu  = b3 >> 1;
    int bK   = (b3 & 1) * 8 + r8;
    int bNu  = (b3 >> 1) + (wnOff >> 3);

    uint32_t smb = smem_u32(smc);
    uint32_t mbF = smb + MBOFF;
    uint32_t mbE = smb + MBOFF + 64;

    if (tid == 0) {
#pragma unroll
        for (int s = 0; s < NSTG; s++) {
            MBAR_INIT(mbF + s * 8, 1);
            MBAR_INIT(mbE + s * 8, 16);
        }
    }
    __syncthreads();

    auto decomp = [&](int tile, int& e, int& mt, int& n) {
        mt = tile % mtot;
        n = tile / mtot;
        e = 0;
#pragma unroll
        for (int q = 1; q < NEXP; q++)
            if (g_mOff[q] <= mt) e = q;
    };

    auto issue = [&](int gc) {
        int s = gc & (NSTG - 1);
        int tileSeq = gc / NC2;
        int c2 = gc - tileSeq * NC2;
        int tile = bid + tileSeq * nCTA;
        int e, mt, n;
        decomp(tile, e, mt, n);
        const __half* Ab = Apk + ((size_t)mt * NCH + 2 * c2) * ABLK_H;
        const __half* Bb = Bpk + ((size_t)(e * NSTRIPE + n) * NCH + 2 * c2) * BBLK_H;
        uint32_t stg = smb + (uint32_t)s * STG2;
        uint32_t mb = mbF + s * 8;
        MBAR_EXPECT_TX(mb, STG2);
        bulk_ld(stg, Ab, 2 * ABLK_B, mb);
        bulk_ld(stg + 2 * ABLK_B, Bb, 2 * BBLK_B, mb);
    };

    if (tid == 0) {
        int pre = totalStages < NSTG ? totalStages : NSTG;
        for (int c0 = 0; c0 < pre; c0++) issue(c0);
    }

    uint32_t af[2][4][4];
    uint32_t bf[2][4][2];
    int gc = 0;

    for (int tseq = 0; tseq < nMy; tseq++) {
        int tile = bid + tseq * nCTA;
        int e, mt, n;
        decomp(tile, e, mt, n);
        int cnt = g_cnt[e];
        int rowLoc = (mt - g_mOff[e]) * MT;     // local row block within expert

        float acc[4][4][4];
#pragma unroll
        for (int i = 0; i < 4; i++)
#pragma unroll
            for (int j = 0; j < 4; j++)
#pragma unroll
                for (int q = 0; q < 4; q++) acc[i][j][q] = 0.f;

        for (int c2 = 0; c2 < NC2; c2++, gc++) {
            int s = gc & (NSTG - 1);
            int par = (gc >> 2) & 1;
            MBAR_WAIT(mbF + s * 8, par);
            DO_STAGE(s);
            if (tid == 0 && gc + NSTG < totalStages) {
                MBAR_WAIT(mbE + s * 8, par);
                issue(gc + NSTG);
            }
        }

        // epilogue
        const float* bias = biasAll + (size_t)e * N;
        int colBlock = n * NT;
#pragma unroll
        for (int nb = 0; nb < 4; nb++) {
            int col = colBlock + wnOff + nb * 8 + tg * 2;
            float2 bv = *(const float2*)(bias + col);
#pragma unroll
            for (int mb = 0; mb < 4; mb++) {
                int mr = wmOff + mb * 16 + g;
#pragma unroll
                for (int h = 0; h < 2; h++) {
                    int rr2 = mr + h * 8;
                    if (rowLoc + rr2 < cnt) {
                        float ox = acc[mb][nb][2 * h]     + bv.x;
                        float oy = acc[mb][nb][2 * h + 1] + bv.y;
                        if (RELU) { ox = fmaxf(ox, 0.f); oy = fmaxf(oy, 0.f); }
                        int R = mt * MT + rr2;            // global padded row
                        if (OUT == 1) {
                            __half* dst = (__half*)Cout +
                                (size_t)((R >> 7) * (N / 32) + (col >> 5)) * ABLK_H +
                                (R & 127) * 40 + (col & 31);
                            *(__half2*)dst = __floats2half2_rn(ox, oy);
                        } else {
                            *(float2*)((float*)Cout + (size_t)R * N + col) =
                                make_float2(ox, oy);
                        }
                    }
                }
            }
        }
    }
}

// ---------------- persistent head GEMM (Round-11 proven) ---------------------
#define H_NCH   (DMODEL / KCH)        // 32
#define H_NC2   (DMODEL / (2 * KCH))  // 16
#define H_TM    16
#define H_TN    125
#define H_NTILES (H_TM * H_TN)

__global__ void __launch_bounds__(512, 1)
hgemm_persist(const __half* __restrict__ Apk, const __half* __restrict__ Bpk,
              const float* __restrict__ bias, float* __restrict__ out) {
    extern __shared__ __align__(128) char smc[];
    int bid = blockIdx.x;
    int nCTA = gridDim.x;

    int nMy = (bid < H_NTILES) ? ((H_NTILES - 1 - bid) / nCTA + 1) : 0;
    if (nMy == 0) return;
    int totalStages = nMy * H_NC2;

    int tid = threadIdx.x;
    int wid = tid >> 5, lane = tid & 31;
    int wm = wid >> 3, wn = wid & 7;
    int wmOff = wm * 64, wnOff = wn * 32;
    int g = lane >> 2, tg = lane & 3;
    int b3 = lane >> 3, r8 = lane & 7;
    int aRow = (b3 & 1) * 8 + r8;
    int aKu  = b3 >> 1;
    int bK   = (b3 & 1) * 8 + r8;
    int bNu  = (b3 >> 1) + (wnOff >> 3);

    uint32_t smb = smem_u32(smc);
    uint32_t mbF = smb + MBOFF;
    uint32_t mbE = smb + MBOFF + 64;

    if (tid == 0) {
#pragma unroll
        for (int s = 0; s < NSTG; s++) {
            MBAR_INIT(mbF + s * 8, 1);
            MBAR_INIT(mbE + s * 8, 16);
        }
    }
    __syncthreads();

    auto issue = [&](int gc) {
        int s = gc & (NSTG - 1);
        int tileSeq = gc / H_NC2;
        int c2 = gc - tileSeq * H_NC2;
        int tile = bid + tileSeq * nCTA;
        int m = tile & (H_TM - 1);
        int n = tile >> 4;
        const __half* Ab = Apk + ((size_t)m * H_NCH + 2 * c2) * ABLK_H;
        const __half* Bb = Bpk + ((size_t)n * H_NCH + 2 * c2) * BBLK_H;
        uint32_t stg = smb + (uint32_t)s * STG2;
        uint32_t mb = mbF + s * 8;
        MBAR_EXPECT_TX(mb, STG2);
        bulk_ld(stg, Ab, 2 * ABLK_B, mb);
        bulk_ld(stg + 2 * ABLK_B, Bb, 2 * BBLK_B, mb);
    };

    if (tid == 0) {
        int pre = totalStages < NSTG ? totalStages : NSTG;
        for (int c0 = 0; c0 < pre; c0++) issue(c0);
    }

    uint32_t af[2][4][4];
    uint32_t bf[2][4][2];
    int gc = 0;

    for (int tile = bid; tile < H_NTILES; tile += nCTA) {
        int m = tile & (H_TM - 1);
        int n = tile >> 4;

        float acc[4][4][4];
#pragma unroll
        for (int i = 0; i < 4; i++)
#pragma unroll
            for (int j = 0; j < 4; j++)
#pragma unroll
                for (int q = 0; q < 4; q++) acc[i][j][q] = 0.f;

        for (int c2 = 0; c2 < H_NC2; c2++, gc++) {
            int s = gc & (NSTG - 1);
            int par = (gc >> 2) & 1;
            MBAR_WAIT(mbF + s * 8, par);
            DO_STAGE(s);
            if (tid == 0 && gc + NSTG < totalStages) {
                MBAR_WAIT(mbE + s * 8, par);
                issue(gc + NSTG);
            }
        }

        // epilogue (all head rows valid; M=2048 exact)
        int rowBase = m * MT;
        int colBase = n * NT;
#pragma unroll
        for (int nb = 0; nb < 4; nb++) {
            int col = colBase + wnOff + nb * 8 + tg * 2;
            float2 bv = *(const float2*)(bias + col);
#pragma unroll
            for (int mb = 0; mb < 4; mb++) {
                int mr = rowBase + wmOff + mb * 16 + g;
#pragma unroll
                for (int h = 0; h < 2; h++) {
                    float ox = acc[mb][nb][2 * h]     + bv.x;
                    float oy = acc[mb][nb][2 * h + 1] + bv.y;
                    *(float2*)(out + (size_t)(mr + h * 8) * VOCABSZ + col) =
                        make_float2(ox, oy);
                }
            }
        }
    }
}

// ---------------- launch ----------------------------------------------------
extern "C" void kernel_launch(void* const* d_in, const int* in_sizes, int n_in,
                              void* d_out, int out_size) {
    const int*   x     = (const int*)  d_in[0];
    const float* embed = (const float*)d_in[1];
    const float* Wg    = (const float*)d_in[2];
    const float* bg    = (const float*)d_in[3];
    const float* W1    = (const float*)d_in[4];
    const float* b1    = (const float*)d_in[5];
    const float* W2    = (const float*)d_in[6];
    const float* b2    = (const float*)d_in[7];
    const float* gamma = (const float*)d_in[8];
    const float* beta  = (const float*)d_in[9];
    const float* Wh    = (const float*)d_in[10];
    const float* bh    = (const float*)d_in[11];
    float* out = (float*)d_out;

    __half *p_hpk, *p_apk, *p_xpk, *p_Whp, *p_W1p, *p_W2p;
    float *p_y;
    cudaGetSymbolAddress((void**)&p_hpk, g_hpk);
    cudaGetSymbolAddress((void**)&p_apk, g_apk);
    cudaGetSymbolAddress((void**)&p_xpk, g_xpk);
    cudaGetSymbolAddress((void**)&p_Whp, g_Whp);
    cudaGetSymbolAddress((void**)&p_W1p, g_W1p);
    cudaGetSymbolAddress((void**)&p_W2p, g_W2p);
    cudaGetSymbolAddress((void**)&p_y,   g_y);

    cudaFuncSetAttribute((const void*)fgemm_persist<DMODEL, HIDDEN, true, 1>,
                         cudaFuncAttributeMaxDynamicSharedMemorySize, SMEM_SZ);
    cudaFuncSetAttribute((const void*)fgemm_persist<HIDDEN, DMODEL, false, 0>,
                         cudaFuncAttributeMaxDynamicSharedMemorySize, SMEM_SZ);
    cudaFuncSetAttribute((const void*)hgemm_persist,
                         cudaFuncAttributeMaxDynamicSharedMemorySize, SMEM_SZ);

    prep_kernel<<<WBLOCKS + TOKENS, 256>>>(x, embed, Wg, bg, Wh, W1, W2);
    scan_assign_kernel<<<1, 1024>>>();
    pack_h_kernel<<<(NSLOTPAD * 128 + 255) / 256, 256>>>(x, embed);

    // FFN1: persistent grouped [cnt,1024] x [1024,2048], ReLU, packed-half out
    fgemm_persist<DMODEL, HIDDEN, true, 1>
        <<<NSM, 512, SMEM_SZ>>>(p_hpk, p_W1p, b1, p_apk);
    // FFN2: persistent grouped [cnt,2048] x [2048,1024], fp32 out
    fgemm_persist<HIDDEN, DMODEL, false, 0>
        <<<NSM, 512, SMEM_SZ>>>(p_apk, p_W2p, b2, p_y);

    combine_ln_kernel<<<TOKENS, 256>>>(gamma, beta);

    hgemm_persist<<<NSM, 512, SMEM_SZ>>>(p_xpk, p_Whp, bh, out);
}